// round 15
// baseline (speedup 1.0000x reference)
#include <cuda_runtime.h>
#include <cuda_bf16.h>
#include <math.h>

#define NLOC 8192
#define SEQ 32
#define CDIM 128
#define NHEAD 8
#define HD 16
#define MROWS (NLOC*SEQ)   // 262144
#define FFND 512

// -------- weights (bf16, n-major) --------
__device__ __nv_bfloat16 g_w1tb[(size_t)FFND * CDIM];   // w1^T [512][128]
__device__ __nv_bfloat16 g_w2tb[(size_t)CDIM * FFND];   // w2^T [128][512]
__device__ __nv_bfloat16 g_wqtb[(size_t)CDIM * CDIM];
__device__ __nv_bfloat16 g_wktb[(size_t)CDIM * CDIM];
__device__ __nv_bfloat16 g_wvtb[(size_t)CDIM * CDIM];

// ======================= mma / cp.async helpers =======================
__device__ __forceinline__ void mma16(float* c, const unsigned* a, const unsigned* b) {
    asm volatile(
        "mma.sync.aligned.m16n8k16.row.col.f32.bf16.bf16.f32 "
        "{%0,%1,%2,%3}, {%4,%5,%6,%7}, {%8,%9}, {%0,%1,%2,%3};"
        : "+f"(c[0]), "+f"(c[1]), "+f"(c[2]), "+f"(c[3])
        : "r"(a[0]), "r"(a[1]), "r"(a[2]), "r"(a[3]),
          "r"(b[0]), "r"(b[1]));
}

__device__ __forceinline__ void cp16(void* s, const void* g) {
    unsigned saddr = (unsigned)__cvta_generic_to_shared(s);
    asm volatile("cp.async.cg.shared.global [%0], [%1], 16;" :: "r"(saddr), "l"(g));
}
__device__ __forceinline__ void cp_commit() {
    asm volatile("cp.async.commit_group;");
}
template<int N>
__device__ __forceinline__ void cp_wait() {
    asm volatile("cp.async.wait_group %0;" :: "n"(N));
}

typedef unsigned long long u64t;
__device__ __forceinline__ u64t pk2(float lo, float hi) {
    u64t r; asm("mov.b64 %0,{%1,%2};" : "=l"(r) : "f"(lo), "f"(hi)); return r;
}
__device__ __forceinline__ void upk2(u64t v, float& lo, float& hi) {
    asm("mov.b64 {%0,%1},%2;" : "=f"(lo), "=f"(hi) : "l"(v));
}
__device__ __forceinline__ void fma2(u64t& d, u64t a, u64t b) {
    asm("fma.rn.f32x2 %0,%1,%2,%0;" : "+l"(d) : "l"(a), "l"(b));
}

// ============================================================
// Kernel 0: transpose + convert all weights to bf16 (n-major)
// ============================================================
__global__ void k_wtb(const float* __restrict__ w1, const float* __restrict__ w2,
                      const float* __restrict__ wq, const float* __restrict__ wk,
                      const float* __restrict__ wv)
{
    __shared__ float t[32][33];
    const int which = blockIdx.z;
    const float* srcs[5] = { w1, w2, wq, wk, wv };
    __nv_bfloat16* dsts[5] = { g_w1tb, g_w2tb, g_wqtb, g_wktb, g_wvtb };
    const int Rs[5] = { 128, 512, 128, 128, 128 };
    const int Cs[5] = { 512, 128, 128, 128, 128 };
    const float* src = srcs[which];
    __nv_bfloat16* dst = dsts[which];
    const int R = Rs[which], C = Cs[which];
    const int r0 = blockIdx.y * 32, c0 = blockIdx.x * 32;
    if (r0 >= R || c0 >= C) return;
    const int lx = threadIdx.x, ly = threadIdx.y;
#pragma unroll
    for (int i = 0; i < 32; i += 8)
        t[ly + i][lx] = src[(size_t)(r0 + ly + i) * C + c0 + lx];
    __syncthreads();
#pragma unroll
    for (int i = 0; i < 32; i += 8)
        dst[(size_t)(c0 + ly + i) * R + r0 + lx] = __float2bfloat16(t[lx][ly + i]);
}

// ============================================================
// mma pass: OUT(64x128) warp-tiled 32x32 (warps 2x4)
// ============================================================
#define A_W 68

__device__ __forceinline__ void f_mma_pass(const unsigned* __restrict__ As,
                                           const unsigned* __restrict__ Bs,
                                           float acc[2][4][4],
                                           int wm, int wn, int g, int t)
{
#pragma unroll
    for (int s = 0; s < 8; s++) {
        unsigned aw[2][4];
#pragma unroll
        for (int mf = 0; mf < 2; mf++) {
            const int row = wm * 32 + mf * 16 + g;
            aw[mf][0] = As[row * A_W + s * 8 + t];
            aw[mf][1] = As[(row + 8) * A_W + s * 8 + t];
            aw[mf][2] = As[row * A_W + s * 8 + t + 4];
            aw[mf][3] = As[(row + 8) * A_W + s * 8 + t + 4];
        }
#pragma unroll
        for (int nf = 0; nf < 4; nf++) {
            const int n = wn * 32 + nf * 8 + g;
            unsigned bw[2];
            bw[0] = Bs[n * A_W + s * 8 + t];
            bw[1] = Bs[n * A_W + s * 8 + t + 4];
#pragma unroll
            for (int mf = 0; mf < 2; mf++)
                mma16(acc[mf][nf], aw[mf], bw);
        }
    }
}

__device__ __forceinline__ void f_mma_pass2(const unsigned* __restrict__ As,
                                            const unsigned* __restrict__ Bs0,
                                            const unsigned* __restrict__ Bs1,
                                            float acc0[2][4][4], float acc1[2][4][4],
                                            int wm, int wn, int g, int t)
{
#pragma unroll
    for (int s = 0; s < 8; s++) {
        unsigned aw[2][4];
#pragma unroll
        for (int mf = 0; mf < 2; mf++) {
            const int row = wm * 32 + mf * 16 + g;
            aw[mf][0] = As[row * A_W + s * 8 + t];
            aw[mf][1] = As[(row + 8) * A_W + s * 8 + t];
            aw[mf][2] = As[row * A_W + s * 8 + t + 4];
            aw[mf][3] = As[(row + 8) * A_W + s * 8 + t + 4];
        }
#pragma unroll
        for (int nf = 0; nf < 4; nf++) {
            const int n = wn * 32 + nf * 8 + g;
            unsigned bw0[2], bw1[2];
            bw0[0] = Bs0[n * A_W + s * 8 + t];
            bw0[1] = Bs0[n * A_W + s * 8 + t + 4];
            bw1[0] = Bs1[n * A_W + s * 8 + t];
            bw1[1] = Bs1[n * A_W + s * 8 + t + 4];
#pragma unroll
            for (int mf = 0; mf < 2; mf++) {
                mma16(acc0[mf][nf], aw[mf], bw0);
                mma16(acc1[mf][nf], aw[mf], bw1);
            }
        }
    }
}

// ============================================================
// MEGA KERNEL: QKV + rotary + attention + LN1 + FFN + LN2
// 256 thr / 8 warps (2x4), CTA = 64 rows, 2 CTAs/SM.
//
// smem (words, total 26112 = 104448 B):
//  QKV:   A 4352 @0 | Bk 8704 @4352 | Bv 8704 @13056
//  Attn:  Kbuf f32 8448 @0 | Vbuf 8448 @8448 | Qbuf 8448 @16896
//  FFN:   x1b 4352 @0 | Hc 4352 @4352 | B0(w1) 8704 @8704 | B1(w2) 8704 @17408
//  Epi:   T f32 8448 @0 (x1 residual lives in REGISTERS)
// ============================================================
#define FB0 4352
#define FB1 13056
#define MG_X1B 0
#define MG_HC  4352
#define MG_B0  8704
#define MG_B1  17408
#define MG_WORDS 26112
#define MG_BYTES (MG_WORDS*4)
#define FP 132

__device__ __forceinline__ void f_stage_w(unsigned* sm_u, int dstoff,
                                          const __nv_bfloat16* W, int tid)
{
#pragma unroll
    for (int j = 0; j < 8; j++) {
        const int i = tid + j * 256;
        const int row = i >> 4, u = i & 15;
        cp16(&sm_u[dstoff + row * A_W + u * 4], &W[(size_t)row * CDIM + u * 8]);
    }
    cp_commit();
}

__device__ __forceinline__ void ff_stage_w1(unsigned* sm_u, int nt, int tid)
{
#pragma unroll
    for (int j = 0; j < 8; j++) {
        const int i = tid + j * 256;
        const int row = i >> 4, u = i & 15;
        cp16(&sm_u[MG_B0 + row * A_W + u * 4],
             &g_w1tb[(size_t)(nt * 128 + row) * CDIM + u * 8]);
    }
    cp_commit();
}
__device__ __forceinline__ void ff_stage_w2(unsigned* sm_u, int nt, int tid)
{
#pragma unroll
    for (int j = 0; j < 8; j++) {
        const int i = tid + j * 256;
        const int row = i >> 4, u = i & 15;
        cp16(&sm_u[MG_B1 + row * A_W + u * 4],
             &g_w2tb[(size_t)row * FFND + nt * 128 + u * 8]);
    }
    cp_commit();
}

__global__ __launch_bounds__(256, 2)
void k_block(const float* __restrict__ x,
             const float* __restrict__ bq, const float* __restrict__ bk,
             const float* __restrict__ bv,
             const float* __restrict__ ln1g, const float* __restrict__ ln1b,
             const float* __restrict__ b1, const float* __restrict__ b2,
             const float* __restrict__ ln2g, const float* __restrict__ ln2b,
             float* __restrict__ out)
{
    extern __shared__ unsigned sm_u[];
    float* smf = (float*)sm_u;
    __shared__ float sinT[SEQ][8];
    __shared__ float cosT[SEQ][8];

    float* Kbuf = smf;
    float* Vbuf = smf + 8448;
    float* Qbuf = smf + 16896;

    const int tid = threadIdx.x;
    const int warp = tid >> 5, lane = tid & 31;
    const int wm = warp >> 2, wn = warp & 3;
    const int g = lane >> 2, t = lane & 3;
    const int m0 = blockIdx.x * 64;

    if (tid < SEQ * 8) {
        const int s = tid >> 3, j = tid & 7;
        const float ang = powf(10000.0f, -(float)j / 7.0f);
        float sv, cv;
        sincosf((float)s * ang, &sv, &cv);
        sinT[s][j] = sv;
        cosT[s][j] = cv;
    }

    // ================= Phase 1: QKV GEMM =================
    f_stage_w(sm_u, FB0, g_wktb, tid);
    f_stage_w(sm_u, FB1, g_wvtb, tid);
    {
        const int row = tid >> 2;
        const int seg = tid & 3;
        const int r = m0 + row;
        const float* src = &x[(size_t)(r & 31) * (NLOC * CDIM)
                              + (size_t)(r >> 5) * CDIM + seg * 32];
        unsigned* dstw = &sm_u[row * A_W + seg * 16];
#pragma unroll
        for (int q = 0; q < 8; q++) {
            float4 v = *(const float4*)(src + q * 4);
            __nv_bfloat162 b0 = __floats2bfloat162_rn(v.x, v.y);
            __nv_bfloat162 b1c = __floats2bfloat162_rn(v.z, v.w);
            dstw[q * 2]     = *(unsigned*)&b0;
            dstw[q * 2 + 1] = *(unsigned*)&b1c;
        }
    }
    cp_wait<0>();
    __syncthreads();

    float acc[3][2][4][4];
#pragma unroll
    for (int w = 0; w < 3; w++)
#pragma unroll
        for (int i = 0; i < 2; i++)
#pragma unroll
            for (int j = 0; j < 4; j++)
#pragma unroll
                for (int q = 0; q < 4; q++) acc[w][i][j][q] = 0.0f;

    f_mma_pass2(sm_u, &sm_u[FB0], &sm_u[FB1], acc[0], acc[1], wm, wn, g, t);
    __syncthreads();

    f_stage_w(sm_u, FB0, g_wqtb, tid);
    cp_wait<0>();
    __syncthreads();
    f_mma_pass(sm_u, &sm_u[FB0], acc[2], wm, wn, g, t);
    __syncthreads();

    {
        const float* biases[3] = { bk, bv, bq };
        float* dsts[3] = { Kbuf, Vbuf, Qbuf };
#pragma unroll
        for (int w = 0; w < 3; w++) {
            float* dst = dsts[w];
            const float* BIAS = biases[w];
#pragma unroll
            for (int nf = 0; nf < 4; nf++) {
                const int col = wn * 32 + nf * 8 + 2 * t;
                const float2 bv2 = *(const float2*)&BIAS[col];
#pragma unroll
                for (int mf = 0; mf < 2; mf++) {
                    const int row0 = wm * 32 + mf * 16 + g;
                    float2 o0, o1;
                    o0.x = acc[w][mf][nf][0] + bv2.x; o0.y = acc[w][mf][nf][1] + bv2.y;
                    o1.x = acc[w][mf][nf][2] + bv2.x; o1.y = acc[w][mf][nf][3] + bv2.y;
                    *(float2*)&dst[row0 * FP + col] = o0;
                    *(float2*)&dst[(row0 + 8) * FP + col] = o1;
                }
            }
        }
    }
    __syncthreads();

    // ================= Phase 2: rotary + attention =================
#pragma unroll
    for (int task = tid; task < 64 * NHEAD; task += 256) {
        const int row = task >> 3, h = task & 7;
        const int s = row & 31;
        float tq[HD], tk[HD];
#pragma unroll
        for (int d4 = 0; d4 < 4; d4++) {
            *(float4*)&tq[d4 * 4] = *(const float4*)&Qbuf[row * FP + h * 16 + d4 * 4];
            *(float4*)&tk[d4 * 4] = *(const float4*)&Kbuf[row * FP + h * 16 + d4 * 4];
        }
        float rq[HD], rk[HD];
#pragma unroll
        for (int d = 0; d < HD; d++) {
            const float sv = sinT[s][d >> 1];
            const float cv = cosT[s][d >> 1];
            const int pc = (d < 8) ? (2 * d + 1) : (2 * d - 16);
            const float sgn = (d < 8) ? -1.0f : 1.0f;
            rq[d] = tq[d] * cv + sgn * tq[pc] * sv;
            rk[d] = tk[d] * cv + sgn * tk[pc] * sv;
        }
#pragma unroll
        for (int d4 = 0; d4 < 4; d4++) {
            *(float4*)&Qbuf[row * FP + h * 16 + d4 * 4] = *(const float4*)&rq[d4 * 4];
            *(float4*)&Kbuf[row * FP + h * 16 + d4 * 4] = *(const float4*)&rk[d4 * 4];
        }
    }
    __syncthreads();

    const int h = warp;
    const float decay = log1pf(-exp2f(-(1.0f + 3.0f * (float)h / 8.0f)));

#pragma unroll
    for (int l = 0; l < 2; l++) {
        const int qrow = l * 32 + lane;

        u64t q2[8];
        {
            const float* qp = &Qbuf[qrow * FP + h * 16];
            ulonglong2 qa = *(const ulonglong2*)(qp);
            ulonglong2 qb = *(const ulonglong2*)(qp + 4);
            ulonglong2 qc = *(const ulonglong2*)(qp + 8);
            ulonglong2 qd = *(const ulonglong2*)(qp + 12);
            q2[0] = qa.x; q2[1] = qa.y; q2[2] = qb.x; q2[3] = qb.y;
            q2[4] = qc.x; q2[5] = qc.y; q2[6] = qd.x; q2[7] = qd.y;
        }

        float p[SEQ];
        float mx = -1e30f;
#pragma unroll
        for (int j = 0; j < SEQ; j++) {
            const float* kp = &Kbuf[(l * 32 + j) * FP + h * 16];
            ulonglong2 ka = *(const ulonglong2*)(kp);
            ulonglong2 kb = *(const ulonglong2*)(kp + 4);
            ulonglong2 kc = *(const ulonglong2*)(kp + 8);
            ulonglong2 kd = *(const ulonglong2*)(kp + 12);
            u64t s2a = 0ull, s2b = 0ull;
            fma2(s2a, q2[0], ka.x); fma2(s2b, q2[1], ka.y);
            fma2(s2a, q2[2], kb.x); fma2(s2b, q2[3], kb.y);
            fma2(s2a, q2[4], kc.x); fma2(s2b, q2[5], kc.y);
            fma2(s2a, q2[6], kd.x); fma2(s2b, q2[7], kd.y);
            float la, ha, lb, hb;
            upk2(s2a, la, ha);
            upk2(s2b, lb, hb);
            const float dot = (la + lb) + (ha + hb) + fabsf((float)(lane - j)) * decay;
            p[j] = dot;
            mx = fmaxf(mx, dot);
        }
        float sum = 0.0f;
#pragma unroll
        for (int j = 0; j < SEQ; j++) { p[j] = expf(p[j] - mx); sum += p[j]; }
        const float inv = 1.0f / sum;

        u64t o2[8];
#pragma unroll
        for (int i = 0; i < 8; i++) o2[i] = 0ull;
#pragma unroll
        for (int j = 0; j < SEQ; j++) {
            const float* vp = &Vbuf[(l * 32 + j) * FP + h * 16];
            ulonglong2 va = *(const ulonglong2*)(vp);
            ulonglong2 vb = *(const ulonglong2*)(vp + 4);
            ulonglong2 vc = *(const ulonglong2*)(vp + 8);
            ulonglong2 vd = *(const ulonglong2*)(vp + 12);
            const u64t pj2 = pk2(p[j], p[j]);
            fma2(o2[0], va.x, pj2); fma2(o2[1], va.y, pj2);
            fma2(o2[2], vb.x, pj2); fma2(o2[3], vb.y, pj2);
            fma2(o2[4], vc.x, pj2); fma2(o2[5], vc.y, pj2);
            fma2(o2[6], vd.x, pj2); fma2(o2[7], vd.y, pj2);
        }
        float o[HD];
#pragma unroll
        for (int i = 0; i < 8; i++) {
            float lo, hi;
            upk2(o2[i], lo, hi);
            o[2 * i] = lo * inv;
            o[2 * i + 1] = hi * inv;
        }
#pragma unroll
        for (int d4 = 0; d4 < 4; d4++)
            *(float4*)&Qbuf[qrow * FP + h * 16 + d4 * 4] = *(const float4*)&o[d4 * 4];
    }
    __syncthreads();

    // ====== Phase 3: residual + LN1 -> registers (xres) + smem x1b (bf16) ======
    float xres[8][4];
#pragma unroll
    for (int rr = 0; rr < 8; rr++) {
        const int row = warp * 8 + rr;
        const int r = m0 + row;
        const int c = lane * 4;
        float4 ov = *(const float4*)&Qbuf[row * FP + c];
        float4 xv = *(const float4*)&x[(size_t)(r & 31) * (NLOC * CDIM) + (size_t)(r >> 5) * CDIM + c];
        float v0 = ov.x + xv.x, v1 = ov.y + xv.y, v2 = ov.z + xv.z, v3 = ov.w + xv.w;
        float sum = v0 + v1 + v2 + v3;
        float sq  = v0 * v0 + v1 * v1 + v2 * v2 + v3 * v3;
#pragma unroll
        for (int off = 16; off > 0; off >>= 1) {
            sum += __shfl_xor_sync(0xffffffffu, sum, off);
            sq  += __shfl_xor_sync(0xffffffffu, sq,  off);
        }
        const float mu  = sum * (1.0f / 128.0f);
        const float var = sq * (1.0f / 128.0f) - mu * mu;
        const float wnr = rsqrtf(var + 1e-5f);
        float4 g4 = *(const float4*)&ln1g[c];
        float4 b4 = *(const float4*)&ln1b[c];
        float o0 = (v0 - mu) * wnr * g4.x + b4.x;
        float o1 = (v1 - mu) * wnr * g4.y + b4.y;
        float o2v = (v2 - mu) * wnr * g4.z + b4.z;
        float o3 = (v3 - mu) * wnr * g4.w + b4.w;
        xres[rr][0] = o0; xres[rr][1] = o1; xres[rr][2] = o2v; xres[rr][3] = o3;
        __nv_bfloat162 p0 = __floats2bfloat162_rn(o0, o1);
        __nv_bfloat162 p1 = __floats2bfloat162_rn(o2v, o3);
        sm_u[MG_X1B + row * A_W + (c >> 1)]     = *(unsigned*)&p0;
        sm_u[MG_X1B + row * A_W + (c >> 1) + 1] = *(unsigned*)&p1;
    }
    __syncthreads();   // x1b complete; K/V/Q buffers dead

    // ======= Phase 4: FFN, fixed-role double buffer (B0=w1, B1=w2) =======
    float acc2[2][4][4];
#pragma unroll
    for (int i = 0; i < 2; i++)
#pragma unroll
        for (int j = 0; j < 4; j++)
#pragma unroll
            for (int q = 0; q < 4; q++) acc2[i][j][q] = 0.0f;

    ff_stage_w1(sm_u, 0, tid);   // w1[0] -> B0
    cp_wait<0>();
    __syncthreads();

#pragma unroll 1
    for (int nt = 0; nt < 4; nt++) {
        // prefetch w2[nt] -> B1 while computing H from B0 (w1[nt]).
        // B1's previous reads (acc2 of nt-1) completed at loop-end sync.
        ff_stage_w2(sm_u, nt, tid);

        float accH[2][4][4];
#pragma unroll
        for (int i = 0; i < 2; i++)
#pragma unroll
            for (int j = 0; j < 4; j++)
#pragma unroll
                for (int q = 0; q < 4; q++) accH[i][j][q] = 0.0f;
        f_mma_pass(&sm_u[MG_X1B], &sm_u[MG_B0], accH, wm, wn, g, t);

        // bias + relu -> Hc (bf16)
#pragma unroll
        for (int nf = 0; nf < 4; nf++) {
            const int col = wn * 32 + nf * 8 + 2 * t;
            const float2 bb = *(const float2*)&b1[nt * 128 + col];
#pragma unroll
            for (int mf = 0; mf < 2; mf++) {
                const int row0 = wm * 32 + mf * 16 + g;
                float h00 = fmaxf(accH[mf][nf][0] + bb.x, 0.0f);
                float h01 = fmaxf(accH[mf][nf][1] + bb.y, 0.0f);
                float h10 = fmaxf(accH[mf][nf][2] + bb.x, 0.0f);
                float h11 = fmaxf(accH[mf][nf][3] + bb.y, 0.0f);
                __nv_bfloat162 p0 = __floats2bfloat162_rn(h00, h01);
                __nv_bfloat162 p1 = __floats2bfloat162_rn(h10, h11);
                sm_u[MG_HC + row0 * A_W + (col >> 1)]       = *(unsigned*)&p0;
                sm_u[MG_HC + (row0 + 8) * A_W + (col >> 1)] = *(unsigned*)&p1;
            }
        }
        cp_wait<0>();      // w2[nt] arrived in B1
        __syncthreads();   // Hc visible; B0's w1[nt] reads done

        // prefetch w1[nt+1] -> B0 while computing acc2 from B1 (w2[nt])
        if (nt < 3)
            ff_stage_w1(sm_u, nt + 1, tid);

        f_mma_pass(&sm_u[MG_HC], &sm_u[MG_B1], acc2, wm, wn, g, t);

        cp_wait<0>();      // w1[nt+1] arrived in B0
        __syncthreads();   // Hc/B1 reads done before next overwrite
    }

    // ================= Phase 5: epilogue =================
    float* T = smf;   // overlays x1b+Hc (dead)
#pragma unroll
    for (int nf = 0; nf < 4; nf++) {
        const int col = wn * 32 + nf * 8 + 2 * t;
        const float2 bb = *(const float2*)&b2[col];
#pragma unroll
        for (int mf = 0; mf < 2; mf++) {
            const int row0 = wm * 32 + mf * 16 + g;
            float2 o0, o1;
            o0.x = acc2[mf][nf][0] + bb.x; o0.y = acc2[mf][nf][1] + bb.y;
            o1.x = acc2[mf][nf][2] + bb.x; o1.y = acc2[mf][nf][3] + bb.y;
            *(float2*)&T[row0 * FP + col] = o0;
            *(float2*)&T[(row0 + 8) * FP + col] = o1;
        }
    }
    __syncthreads();

#pragma unroll
    for (int rr = 0; rr < 8; rr++) {
        const int row = warp * 8 + rr;
        const int r = m0 + row;
        const int c = lane * 4;
        float4 v = *(const float4*)&T[row * FP + c];
        float v0 = v.x + xres[rr][0], v1 = v.y + xres[rr][1];
        float v2 = v.z + xres[rr][2], v3 = v.w + xres[rr][3];
        float sum = v0 + v1 + v2 + v3;
        float sq  = v0 * v0 + v1 * v1 + v2 * v2 + v3 * v3;
#pragma unroll
        for (int off = 16; off > 0; off >>= 1) {
            sum += __shfl_xor_sync(0xffffffffu, sum, off);
            sq  += __shfl_xor_sync(0xffffffffu, sq,  off);
        }
        const float mu  = sum * (1.0f / 128.0f);
        const float var = sq * (1.0f / 128.0f) - mu * mu;
        const float wnr = rsqrtf(var + 1e-5f);
        float4 g4 = *(const float4*)&ln2g[c];
        float4 b4 = *(const float4*)&ln2b[c];
        float4 o;
        o.x = (v0 - mu) * wnr * g4.x + b4.x;
        o.y = (v1 - mu) * wnr * g4.y + b4.y;
        o.z = (v2 - mu) * wnr * g4.z + b4.z;
        o.w = (v3 - mu) * wnr * g4.w + b4.w;
        const int nn = r >> 5;
        const int ss = r & 31;
        *(float4*)&out[(size_t)ss * NLOC * CDIM + (size_t)nn * CDIM + c] = o;
    }
}

// ============================================================
extern "C" void kernel_launch(void* const* d_in, const int* in_sizes, int n_in,
                              void* d_out, int out_size)
{
    (void)in_sizes; (void)n_in; (void)out_size;
    const float* x    = (const float*)d_in[0];
    const float* wq   = (const float*)d_in[1];
    const float* bq   = (const float*)d_in[2];
    const float* wk   = (const float*)d_in[3];
    const float* bk   = (const float*)d_in[4];
    const float* wv   = (const float*)d_in[5];
    const float* bv   = (const float*)d_in[6];
    const float* ln1g = (const float*)d_in[7];
    const float* ln1b = (const float*)d_in[8];
    const float* w1   = (const float*)d_in[9];
    const float* b1   = (const float*)d_in[10];
    const float* w2   = (const float*)d_in[11];
    const float* b2   = (const float*)d_in[12];
    const float* ln2g = (const float*)d_in[13];
    const float* ln2b = (const float*)d_in[14];
    float* out = (float*)d_out;

    cudaFuncSetAttribute(k_block, cudaFuncAttributeMaxDynamicSharedMemorySize, MG_BYTES);

    dim3 tg(16, 16, 5), tb(32, 8);
    k_wtb<<<tg, tb>>>(w1, w2, wq, wk, wv);

    k_block<<<MROWS / 64, 256, MG_BYTES>>>(x, bq, bk, bv, ln1g, ln1b,
                                           b1, b2, ln2g, ln2b, out);
}

// round 16
// speedup vs baseline: 1.0783x; 1.0783x over previous
#include <cuda_runtime.h>
#include <cuda_bf16.h>
#include <math.h>

#define NLOC 8192
#define SEQ 32
#define CDIM 128
#define NHEAD 8
#define HD 16
#define MROWS (NLOC*SEQ)   // 262144
#define FFND 512

// -------- weights (bf16, n-major) --------
__device__ __nv_bfloat16 g_w1tb[(size_t)FFND * CDIM];   // w1^T [512][128]
__device__ __nv_bfloat16 g_w2tb[(size_t)CDIM * FFND];   // w2^T [128][512]
__device__ __nv_bfloat16 g_wqtb[(size_t)CDIM * CDIM];
__device__ __nv_bfloat16 g_wktb[(size_t)CDIM * CDIM];
__device__ __nv_bfloat16 g_wvtb[(size_t)CDIM * CDIM];

// ======================= mma / cp.async helpers =======================
__device__ __forceinline__ void mma16(float* c, const unsigned* a, const unsigned* b) {
    asm volatile(
        "mma.sync.aligned.m16n8k16.row.col.f32.bf16.bf16.f32 "
        "{%0,%1,%2,%3}, {%4,%5,%6,%7}, {%8,%9}, {%0,%1,%2,%3};"
        : "+f"(c[0]), "+f"(c[1]), "+f"(c[2]), "+f"(c[3])
        : "r"(a[0]), "r"(a[1]), "r"(a[2]), "r"(a[3]),
          "r"(b[0]), "r"(b[1]));
}

__device__ __forceinline__ void ldsm4(unsigned* r, unsigned addr) {
    asm volatile("ldmatrix.sync.aligned.m8n8.x4.shared.b16 {%0,%1,%2,%3}, [%4];"
        : "=r"(r[0]), "=r"(r[1]), "=r"(r[2]), "=r"(r[3]) : "r"(addr));
}

__device__ __forceinline__ void cp16(void* s, const void* g) {
    unsigned saddr = (unsigned)__cvta_generic_to_shared(s);
    asm volatile("cp.async.cg.shared.global [%0], [%1], 16;" :: "r"(saddr), "l"(g));
}
__device__ __forceinline__ void cp_commit() {
    asm volatile("cp.async.commit_group;");
}
template<int N>
__device__ __forceinline__ void cp_wait() {
    asm volatile("cp.async.wait_group %0;" :: "n"(N));
}

typedef unsigned long long u64t;
__device__ __forceinline__ u64t pk2(float lo, float hi) {
    u64t r; asm("mov.b64 %0,{%1,%2};" : "=l"(r) : "f"(lo), "f"(hi)); return r;
}
__device__ __forceinline__ void upk2(u64t v, float& lo, float& hi) {
    asm("mov.b64 {%0,%1},%2;" : "=f"(lo), "=f"(hi) : "l"(v));
}
__device__ __forceinline__ void fma2(u64t& d, u64t a, u64t b) {
    asm("fma.rn.f32x2 %0,%1,%2,%0;" : "+l"(d) : "l"(a), "l"(b));
}

// ============================================================
// Kernel 0: transpose + convert all weights to bf16 (n-major)
// ============================================================
__global__ void k_wtb(const float* __restrict__ w1, const float* __restrict__ w2,
                      const float* __restrict__ wq, const float* __restrict__ wk,
                      const float* __restrict__ wv)
{
    __shared__ float t[32][33];
    const int which = blockIdx.z;
    const float* srcs[5] = { w1, w2, wq, wk, wv };
    __nv_bfloat16* dsts[5] = { g_w1tb, g_w2tb, g_wqtb, g_wktb, g_wvtb };
    const int Rs[5] = { 128, 512, 128, 128, 128 };
    const int Cs[5] = { 512, 128, 128, 128, 128 };
    const float* src = srcs[which];
    __nv_bfloat16* dst = dsts[which];
    const int R = Rs[which], C = Cs[which];
    const int r0 = blockIdx.y * 32, c0 = blockIdx.x * 32;
    if (r0 >= R || c0 >= C) return;
    const int lx = threadIdx.x, ly = threadIdx.y;
#pragma unroll
    for (int i = 0; i < 32; i += 8)
        t[ly + i][lx] = src[(size_t)(r0 + ly + i) * C + c0 + lx];
    __syncthreads();
#pragma unroll
    for (int i = 0; i < 32; i += 8)
        dst[(size_t)(c0 + ly + i) * R + r0 + lx] = __float2bfloat16(t[lx][ly + i]);
}

// ============================================================
// mma pass via ldmatrix: OUT(64x128) warp-tiled 32x32 (warps 2x4)
// A bf16 [64][128] pitch A_W words @aOff; B bf16 n-major [128][128] @bOff
// ============================================================
#define A_W 68

// one-B pass
__device__ __forceinline__ void f_mma_pass(unsigned sbase, int aOff, int bOff,
                                           float acc[2][4][4],
                                           int wm, int wn, int lane)
{
    const int lm = lane & 7, lq = lane >> 3;
    // A: M0 rows0-7/k0, M1 rows8-15/k0, M2 rows0-7/k+8, M3 rows8-15/k+8
    const int arow = wm * 32 + (lq & 1) * 8 + lm;
    const int akw  = (lq >> 1) * 4;
    // B: M0 n0-7/k0, M1 n0-7/k+8, M2 n8-15/k0, M3 n8-15/k+8
    const int brow = wn * 32 + (lq >> 1) * 8 + lm;
    const int bkw  = (lq & 1) * 4;
    unsigned a0 = sbase + (unsigned)((aOff + arow * A_W + akw) << 2);
    unsigned a1 = a0 + 16 * A_W * 4;
    unsigned b0 = sbase + (unsigned)((bOff + brow * A_W + bkw) << 2);
    unsigned b1 = b0 + 16 * A_W * 4;
#pragma unroll
    for (int s = 0; s < 8; s++) {
        unsigned aw0[4], aw1[4], bw0[4], bw1[4];
        ldsm4(aw0, a0 + s * 32);
        ldsm4(aw1, a1 + s * 32);
        ldsm4(bw0, b0 + s * 32);
        ldsm4(bw1, b1 + s * 32);
        mma16(acc[0][0], aw0, bw0);
        mma16(acc[1][0], aw1, bw0);
        mma16(acc[0][1], aw0, bw0 + 2);
        mma16(acc[1][1], aw1, bw0 + 2);
        mma16(acc[0][2], aw0, bw1);
        mma16(acc[1][2], aw1, bw1);
        mma16(acc[0][3], aw0, bw1 + 2);
        mma16(acc[1][3], aw1, bw1 + 2);
    }
}

// two-B pass (shared A fragments)
__device__ __forceinline__ void f_mma_pass2(unsigned sbase, int aOff,
                                            int bOffX, int bOffY,
                                            float accX[2][4][4], float accY[2][4][4],
                                            int wm, int wn, int lane)
{
    const int lm = lane & 7, lq = lane >> 3;
    const int arow = wm * 32 + (lq & 1) * 8 + lm;
    const int akw  = (lq >> 1) * 4;
    const int brow = wn * 32 + (lq >> 1) * 8 + lm;
    const int bkw  = (lq & 1) * 4;
    unsigned a0 = sbase + (unsigned)((aOff + arow * A_W + akw) << 2);
    unsigned a1 = a0 + 16 * A_W * 4;
    unsigned bx0 = sbase + (unsigned)((bOffX + brow * A_W + bkw) << 2);
    unsigned bx1 = bx0 + 16 * A_W * 4;
    unsigned by0 = sbase + (unsigned)((bOffY + brow * A_W + bkw) << 2);
    unsigned by1 = by0 + 16 * A_W * 4;
#pragma unroll
    for (int s = 0; s < 8; s++) {
        unsigned aw0[4], aw1[4], bwx0[4], bwx1[4], bwy0[4], bwy1[4];
        ldsm4(aw0, a0 + s * 32);
        ldsm4(aw1, a1 + s * 32);
        ldsm4(bwx0, bx0 + s * 32);
        ldsm4(bwx1, bx1 + s * 32);
        ldsm4(bwy0, by0 + s * 32);
        ldsm4(bwy1, by1 + s * 32);
        mma16(accX[0][0], aw0, bwx0);     mma16(accX[1][0], aw1, bwx0);
        mma16(accX[0][1], aw0, bwx0 + 2); mma16(accX[1][1], aw1, bwx0 + 2);
        mma16(accX[0][2], aw0, bwx1);     mma16(accX[1][2], aw1, bwx1);
        mma16(accX[0][3], aw0, bwx1 + 2); mma16(accX[1][3], aw1, bwx1 + 2);
        mma16(accY[0][0], aw0, bwy0);     mma16(accY[1][0], aw1, bwy0);
        mma16(accY[0][1], aw0, bwy0 + 2); mma16(accY[1][1], aw1, bwy0 + 2);
        mma16(accY[0][2], aw0, bwy1);     mma16(accY[1][2], aw1, bwy1);
        mma16(accY[0][3], aw0, bwy1 + 2); mma16(accY[1][3], aw1, bwy1 + 2);
    }
}

// ============================================================
// MEGA KERNEL: QKV + rotary + attention + LN1 + FFN + LN2
// (structure identical to Round 15; fragment loads via ldmatrix)
// ============================================================
#define FB0 4352
#define FB1 13056
#define MG_X1B 0
#define MG_HC  4352
#define MG_B0  8704
#define MG_B1  17408
#define MG_WORDS 26112
#define MG_BYTES (MG_WORDS*4)
#define FP 132

__device__ __forceinline__ void f_stage_w(unsigned* sm_u, int dstoff,
                                          const __nv_bfloat16* W, int tid)
{
#pragma unroll
    for (int j = 0; j < 8; j++) {
        const int i = tid + j * 256;
        const int row = i >> 4, u = i & 15;
        cp16(&sm_u[dstoff + row * A_W + u * 4], &W[(size_t)row * CDIM + u * 8]);
    }
    cp_commit();
}

__device__ __forceinline__ void ff_stage_w1(unsigned* sm_u, int nt, int tid)
{
#pragma unroll
    for (int j = 0; j < 8; j++) {
        const int i = tid + j * 256;
        const int row = i >> 4, u = i & 15;
        cp16(&sm_u[MG_B0 + row * A_W + u * 4],
             &g_w1tb[(size_t)(nt * 128 + row) * CDIM + u * 8]);
    }
    cp_commit();
}
__device__ __forceinline__ void ff_stage_w2(unsigned* sm_u, int nt, int tid)
{
#pragma unroll
    for (int j = 0; j < 8; j++) {
        const int i = tid + j * 256;
        const int row = i >> 4, u = i & 15;
        cp16(&sm_u[MG_B1 + row * A_W + u * 4],
             &g_w2tb[(size_t)row * FFND + nt * 128 + u * 8]);
    }
    cp_commit();
}

__global__ __launch_bounds__(256, 2)
void k_block(const float* __restrict__ x,
             const float* __restrict__ bq, const float* __restrict__ bk,
             const float* __restrict__ bv,
             const float* __restrict__ ln1g, const float* __restrict__ ln1b,
             const float* __restrict__ b1, const float* __restrict__ b2,
             const float* __restrict__ ln2g, const float* __restrict__ ln2b,
             float* __restrict__ out)
{
    extern __shared__ unsigned sm_u[];
    float* smf = (float*)sm_u;
    __shared__ float sinT[SEQ][8];
    __shared__ float cosT[SEQ][8];

    float* Kbuf = smf;
    float* Vbuf = smf + 8448;
    float* Qbuf = smf + 16896;

    const unsigned sbase = (unsigned)__cvta_generic_to_shared(sm_u);
    const int tid = threadIdx.x;
    const int warp = tid >> 5, lane = tid & 31;
    const int wm = warp >> 2, wn = warp & 3;
    const int g = lane >> 2, t = lane & 3;
    const int m0 = blockIdx.x * 64;

    if (tid < SEQ * 8) {
        const int s = tid >> 3, j = tid & 7;
        const float ang = powf(10000.0f, -(float)j / 7.0f);
        float sv, cv;
        sincosf((float)s * ang, &sv, &cv);
        sinT[s][j] = sv;
        cosT[s][j] = cv;
    }

    // ================= Phase 1: QKV GEMM =================
    f_stage_w(sm_u, FB0, g_wktb, tid);
    f_stage_w(sm_u, FB1, g_wvtb, tid);
    {
        const int row = tid >> 2;
        const int seg = tid & 3;
        const int r = m0 + row;
        const float* src = &x[(size_t)(r & 31) * (NLOC * CDIM)
                              + (size_t)(r >> 5) * CDIM + seg * 32];
        unsigned* dstw = &sm_u[row * A_W + seg * 16];
#pragma unroll
        for (int q = 0; q < 8; q++) {
            float4 v = *(const float4*)(src + q * 4);
            __nv_bfloat162 b0 = __floats2bfloat162_rn(v.x, v.y);
            __nv_bfloat162 b1c = __floats2bfloat162_rn(v.z, v.w);
            dstw[q * 2]     = *(unsigned*)&b0;
            dstw[q * 2 + 1] = *(unsigned*)&b1c;
        }
    }
    cp_wait<0>();
    __syncthreads();

    float acc[3][2][4][4];
#pragma unroll
    for (int w = 0; w < 3; w++)
#pragma unroll
        for (int i = 0; i < 2; i++)
#pragma unroll
            for (int j = 0; j < 4; j++)
#pragma unroll
                for (int q = 0; q < 4; q++) acc[w][i][j][q] = 0.0f;

    f_mma_pass2(sbase, 0, FB0, FB1, acc[0], acc[1], wm, wn, lane);
    __syncthreads();

    f_stage_w(sm_u, FB0, g_wqtb, tid);
    cp_wait<0>();
    __syncthreads();
    f_mma_pass(sbase, 0, FB0, acc[2], wm, wn, lane);
    __syncthreads();

    {
        const float* biases[3] = { bk, bv, bq };
        float* dsts[3] = { Kbuf, Vbuf, Qbuf };
#pragma unroll
        for (int w = 0; w < 3; w++) {
            float* dst = dsts[w];
            const float* BIAS = biases[w];
#pragma unroll
            for (int nf = 0; nf < 4; nf++) {
                const int col = wn * 32 + nf * 8 + 2 * t;
                const float2 bv2 = *(const float2*)&BIAS[col];
#pragma unroll
                for (int mf = 0; mf < 2; mf++) {
                    const int row0 = wm * 32 + mf * 16 + g;
                    float2 o0, o1;
                    o0.x = acc[w][mf][nf][0] + bv2.x; o0.y = acc[w][mf][nf][1] + bv2.y;
                    o1.x = acc[w][mf][nf][2] + bv2.x; o1.y = acc[w][mf][nf][3] + bv2.y;
                    *(float2*)&dst[row0 * FP + col] = o0;
                    *(float2*)&dst[(row0 + 8) * FP + col] = o1;
                }
            }
        }
    }
    __syncthreads();

    // ================= Phase 2: rotary + attention =================
#pragma unroll
    for (int task = tid; task < 64 * NHEAD; task += 256) {
        const int row = task >> 3, h = task & 7;
        const int s = row & 31;
        float tq[HD], tk[HD];
#pragma unroll
        for (int d4 = 0; d4 < 4; d4++) {
            *(float4*)&tq[d4 * 4] = *(const float4*)&Qbuf[row * FP + h * 16 + d4 * 4];
            *(float4*)&tk[d4 * 4] = *(const float4*)&Kbuf[row * FP + h * 16 + d4 * 4];
        }
        float rq[HD], rk[HD];
#pragma unroll
        for (int d = 0; d < HD; d++) {
            const float sv = sinT[s][d >> 1];
            const float cv = cosT[s][d >> 1];
            const int pc = (d < 8) ? (2 * d + 1) : (2 * d - 16);
            const float sgn = (d < 8) ? -1.0f : 1.0f;
            rq[d] = tq[d] * cv + sgn * tq[pc] * sv;
            rk[d] = tk[d] * cv + sgn * tk[pc] * sv;
        }
#pragma unroll
        for (int d4 = 0; d4 < 4; d4++) {
            *(float4*)&Qbuf[row * FP + h * 16 + d4 * 4] = *(const float4*)&rq[d4 * 4];
            *(float4*)&Kbuf[row * FP + h * 16 + d4 * 4] = *(const float4*)&rk[d4 * 4];
        }
    }
    __syncthreads();

    const int h = warp;
    const float decay = log1pf(-exp2f(-(1.0f + 3.0f * (float)h / 8.0f)));

#pragma unroll
    for (int l = 0; l < 2; l++) {
        const int qrow = l * 32 + lane;

        u64t q2[8];
        {
            const float* qp = &Qbuf[qrow * FP + h * 16];
            ulonglong2 qa = *(const ulonglong2*)(qp);
            ulonglong2 qb = *(const ulonglong2*)(qp + 4);
            ulonglong2 qc = *(const ulonglong2*)(qp + 8);
            ulonglong2 qd = *(const ulonglong2*)(qp + 12);
            q2[0] = qa.x; q2[1] = qa.y; q2[2] = qb.x; q2[3] = qb.y;
            q2[4] = qc.x; q2[5] = qc.y; q2[6] = qd.x; q2[7] = qd.y;
        }

        float p[SEQ];
        float mx = -1e30f;
#pragma unroll
        for (int j = 0; j < SEQ; j++) {
            const float* kp = &Kbuf[(l * 32 + j) * FP + h * 16];
            ulonglong2 ka = *(const ulonglong2*)(kp);
            ulonglong2 kb = *(const ulonglong2*)(kp + 4);
            ulonglong2 kc = *(const ulonglong2*)(kp + 8);
            ulonglong2 kd = *(const ulonglong2*)(kp + 12);
            u64t s2a = 0ull, s2b = 0ull;
            fma2(s2a, q2[0], ka.x); fma2(s2b, q2[1], ka.y);
            fma2(s2a, q2[2], kb.x); fma2(s2b, q2[3], kb.y);
            fma2(s2a, q2[4], kc.x); fma2(s2b, q2[5], kc.y);
            fma2(s2a, q2[6], kd.x); fma2(s2b, q2[7], kd.y);
            float la, ha, lb, hb;
            upk2(s2a, la, ha);
            upk2(s2b, lb, hb);
            const float dot = (la + lb) + (ha + hb) + fabsf((float)(lane - j)) * decay;
            p[j] = dot;
            mx = fmaxf(mx, dot);
        }
        float sum = 0.0f;
#pragma unroll
        for (int j = 0; j < SEQ; j++) { p[j] = expf(p[j] - mx); sum += p[j]; }
        const float inv = 1.0f / sum;

        u64t o2[8];
#pragma unroll
        for (int i = 0; i < 8; i++) o2[i] = 0ull;
#pragma unroll
        for (int j = 0; j < SEQ; j++) {
            const float* vp = &Vbuf[(l * 32 + j) * FP + h * 16];
            ulonglong2 va = *(const ulonglong2*)(vp);
            ulonglong2 vb = *(const ulonglong2*)(vp + 4);
            ulonglong2 vc = *(const ulonglong2*)(vp + 8);
            ulonglong2 vd = *(const ulonglong2*)(vp + 12);
            const u64t pj2 = pk2(p[j], p[j]);
            fma2(o2[0], va.x, pj2); fma2(o2[1], va.y, pj2);
            fma2(o2[2], vb.x, pj2); fma2(o2[3], vb.y, pj2);
            fma2(o2[4], vc.x, pj2); fma2(o2[5], vc.y, pj2);
            fma2(o2[6], vd.x, pj2); fma2(o2[7], vd.y, pj2);
        }
        float o[HD];
#pragma unroll
        for (int i = 0; i < 8; i++) {
            float lo, hi;
            upk2(o2[i], lo, hi);
            o[2 * i] = lo * inv;
            o[2 * i + 1] = hi * inv;
        }
#pragma unroll
        for (int d4 = 0; d4 < 4; d4++)
            *(float4*)&Qbuf[qrow * FP + h * 16 + d4 * 4] = *(const float4*)&o[d4 * 4];
    }
    __syncthreads();

    // ====== Phase 3: residual + LN1 -> registers (xres) + smem x1b (bf16) ======
    float xres[8][4];
#pragma unroll
    for (int rr = 0; rr < 8; rr++) {
        const int row = warp * 8 + rr;
        const int r = m0 + row;
        const int c = lane * 4;
        float4 ov = *(const float4*)&Qbuf[row * FP + c];
        float4 xv = *(const float4*)&x[(size_t)(r & 31) * (NLOC * CDIM) + (size_t)(r >> 5) * CDIM + c];
        float v0 = ov.x + xv.x, v1 = ov.y + xv.y, v2 = ov.z + xv.z, v3 = ov.w + xv.w;
        float sum = v0 + v1 + v2 + v3;
        float sq  = v0 * v0 + v1 * v1 + v2 * v2 + v3 * v3;
#pragma unroll
        for (int off = 16; off > 0; off >>= 1) {
            sum += __shfl_xor_sync(0xffffffffu, sum, off);
            sq  += __shfl_xor_sync(0xffffffffu, sq,  off);
        }
        const float mu  = sum * (1.0f / 128.0f);
        const float var = sq * (1.0f / 128.0f) - mu * mu;
        const float wnr = rsqrtf(var + 1e-5f);
        float4 g4 = *(const float4*)&ln1g[c];
        float4 b4 = *(const float4*)&ln1b[c];
        float o0 = (v0 - mu) * wnr * g4.x + b4.x;
        float o1 = (v1 - mu) * wnr * g4.y + b4.y;
        float o2v = (v2 - mu) * wnr * g4.z + b4.z;
        float o3 = (v3 - mu) * wnr * g4.w + b4.w;
        xres[rr][0] = o0; xres[rr][1] = o1; xres[rr][2] = o2v; xres[rr][3] = o3;
        __nv_bfloat162 p0 = __floats2bfloat162_rn(o0, o1);
        __nv_bfloat162 p1 = __floats2bfloat162_rn(o2v, o3);
        sm_u[MG_X1B + row * A_W + (c >> 1)]     = *(unsigned*)&p0;
        sm_u[MG_X1B + row * A_W + (c >> 1) + 1] = *(unsigned*)&p1;
    }
    __syncthreads();

    // ======= Phase 4: FFN, fixed-role double buffer (B0=w1, B1=w2) =======
    float acc2[2][4][4];
#pragma unroll
    for (int i = 0; i < 2; i++)
#pragma unroll
        for (int j = 0; j < 4; j++)
#pragma unroll
            for (int q = 0; q < 4; q++) acc2[i][j][q] = 0.0f;

    ff_stage_w1(sm_u, 0, tid);
    cp_wait<0>();
    __syncthreads();

#pragma unroll 1
    for (int nt = 0; nt < 4; nt++) {
        ff_stage_w2(sm_u, nt, tid);

        float accH[2][4][4];
#pragma unroll
        for (int i = 0; i < 2; i++)
#pragma unroll
            for (int j = 0; j < 4; j++)
#pragma unroll
                for (int q = 0; q < 4; q++) accH[i][j][q] = 0.0f;
        f_mma_pass(sbase, MG_X1B, MG_B0, accH, wm, wn, lane);

#pragma unroll
        for (int nf = 0; nf < 4; nf++) {
            const int col = wn * 32 + nf * 8 + 2 * t;
            const float2 bb = *(const float2*)&b1[nt * 128 + col];
#pragma unroll
            for (int mf = 0; mf < 2; mf++) {
                const int row0 = wm * 32 + mf * 16 + g;
                float h00 = fmaxf(accH[mf][nf][0] + bb.x, 0.0f);
                float h01 = fmaxf(accH[mf][nf][1] + bb.y, 0.0f);
                float h10 = fmaxf(accH[mf][nf][2] + bb.x, 0.0f);
                float h11 = fmaxf(accH[mf][nf][3] + bb.y, 0.0f);
                __nv_bfloat162 p0 = __floats2bfloat162_rn(h00, h01);
                __nv_bfloat162 p1 = __floats2bfloat162_rn(h10, h11);
                sm_u[MG_HC + row0 * A_W + (col >> 1)]       = *(unsigned*)&p0;
                sm_u[MG_HC + (row0 + 8) * A_W + (col >> 1)] = *(unsigned*)&p1;
            }
        }
        cp_wait<0>();
        __syncthreads();

        if (nt < 3)
            ff_stage_w1(sm_u, nt + 1, tid);

        f_mma_pass(sbase, MG_HC, MG_B1, acc2, wm, wn, lane);

        cp_wait<0>();
        __syncthreads();
    }

    // ================= Phase 5: epilogue =================
    float* T = smf;
#pragma unroll
    for (int nf = 0; nf < 4; nf++) {
        const int col = wn * 32 + nf * 8 + 2 * t;
        const float2 bb = *(const float2*)&b2[col];
#pragma unroll
        for (int mf = 0; mf < 2; mf++) {
            const int row0 = wm * 32 + mf * 16 + g;
            float2 o0, o1;
            o0.x = acc2[mf][nf][0] + bb.x; o0.y = acc2[mf][nf][1] + bb.y;
            o1.x = acc2[mf][nf][2] + bb.x; o1.y = acc2[mf][nf][3] + bb.y;
            *(float2*)&T[row0 * FP + col] = o0;
            *(float2*)&T[(row0 + 8) * FP + col] = o1;
        }
    }
    __syncthreads();

#pragma unroll
    for (int rr = 0; rr < 8; rr++) {
        const int row = warp * 8 + rr;
        const int r = m0 + row;
        const int c = lane * 4;
        float4 v = *(const float4*)&T[row * FP + c];
        float v0 = v.x + xres[rr][0], v1 = v.y + xres[rr][1];
        float v2 = v.z + xres[rr][2], v3 = v.w + xres[rr][3];
        float sum = v0 + v1 + v2 + v3;
        float sq  = v0 * v0 + v1 * v1 + v2 * v2 + v3 * v3;
#pragma unroll
        for (int off = 16; off > 0; off >>= 1) {
            sum += __shfl_xor_sync(0xffffffffu, sum, off);
            sq  += __shfl_xor_sync(0xffffffffu, sq,  off);
        }
        const float mu  = sum * (1.0f / 128.0f);
        const float var = sq * (1.0f / 128.0f) - mu * mu;
        const float wnr = rsqrtf(var + 1e-5f);
        float4 g4 = *(const float4*)&ln2g[c];
        float4 b4 = *(const float4*)&ln2b[c];
        float4 o;
        o.x = (v0 - mu) * wnr * g4.x + b4.x;
        o.y = (v1 - mu) * wnr * g4.y + b4.y;
        o.z = (v2 - mu) * wnr * g4.z + b4.z;
        o.w = (v3 - mu) * wnr * g4.w + b4.w;
        const int nn = r >> 5;
        const int ss = r & 31;
        *(float4*)&out[(size_t)ss * NLOC * CDIM + (size_t)nn * CDIM + c] = o;
    }
}

// ============================================================
extern "C" void kernel_launch(void* const* d_in, const int* in_sizes, int n_in,
                              void* d_out, int out_size)
{
    (void)in_sizes; (void)n_in; (void)out_size;
    const float* x    = (const float*)d_in[0];
    const float* wq   = (const float*)d_in[1];
    const float* bq   = (const float*)d_in[2];
    const float* wk   = (const float*)d_in[3];
    const float* bk   = (const float*)d_in[4];
    const float* wv   = (const float*)d_in[5];
    const float* bv   = (const float*)d_in[6];
    const float* ln1g = (const float*)d_in[7];
    const float* ln1b = (const float*)d_in[8];
    const float* w1   = (const float*)d_in[9];
    const float* b1   = (const float*)d_in[10];
    const float* w2   = (const float*)d_in[11];
    const float* b2   = (const float*)d_in[12];
    const float* ln2g = (const float*)d_in[13];
    const float* ln2b = (const float*)d_in[14];
    float* out = (float*)d_out;

    cudaFuncSetAttribute(k_block, cudaFuncAttributeMaxDynamicSharedMemorySize, MG_BYTES);

    dim3 tg(16, 16, 5), tb(32, 8);
    k_wtb<<<tg, tb>>>(w1, w2, wq, wk, wv);

    k_block<<<MROWS / 64, 256, MG_BYTES>>>(x, bq, bk, bv, ln1g, ln1b,
                                           b1, b2, ln2g, ln2b, out);
}

// round 17
// speedup vs baseline: 1.1383x; 1.0556x over previous
#include <cuda_runtime.h>
#include <cuda_bf16.h>
#include <math.h>

#define NLOC 8192
#define SEQ 32
#define CDIM 128
#define NHEAD 8
#define HD 16
#define MROWS (NLOC*SEQ)   // 262144
#define FFND 512

// -------- weights (bf16, n-major) --------
__device__ __nv_bfloat16 g_w1tb[(size_t)FFND * CDIM];
__device__ __nv_bfloat16 g_w2tb[(size_t)CDIM * FFND];
__device__ __nv_bfloat16 g_wqtb[(size_t)CDIM * CDIM];
__device__ __nv_bfloat16 g_wktb[(size_t)CDIM * CDIM];
__device__ __nv_bfloat16 g_wvtb[(size_t)CDIM * CDIM];

// ======================= mma / cp.async helpers =======================
__device__ __forceinline__ void mma16(float* c, const unsigned* a, const unsigned* b) {
    asm volatile(
        "mma.sync.aligned.m16n8k16.row.col.f32.bf16.bf16.f32 "
        "{%0,%1,%2,%3}, {%4,%5,%6,%7}, {%8,%9}, {%0,%1,%2,%3};"
        : "+f"(c[0]), "+f"(c[1]), "+f"(c[2]), "+f"(c[3])
        : "r"(a[0]), "r"(a[1]), "r"(a[2]), "r"(a[3]),
          "r"(b[0]), "r"(b[1]));
}

__device__ __forceinline__ void ldsm4(unsigned* r, unsigned addr) {
    asm volatile("ldmatrix.sync.aligned.m8n8.x4.shared.b16 {%0,%1,%2,%3}, [%4];"
        : "=r"(r[0]), "=r"(r[1]), "=r"(r[2]), "=r"(r[3]) : "r"(addr));
}

__device__ __forceinline__ void cp16(void* s, const void* g) {
    unsigned saddr = (unsigned)__cvta_generic_to_shared(s);
    asm volatile("cp.async.cg.shared.global [%0], [%1], 16;" :: "r"(saddr), "l"(g));
}
__device__ __forceinline__ void cp_commit() {
    asm volatile("cp.async.commit_group;");
}
template<int N>
__device__ __forceinline__ void cp_wait() {
    asm volatile("cp.async.wait_group %0;" :: "n"(N));
}

typedef unsigned long long u64t;
__device__ __forceinline__ u64t pk2(float lo, float hi) {
    u64t r; asm("mov.b64 %0,{%1,%2};" : "=l"(r) : "f"(lo), "f"(hi)); return r;
}
__device__ __forceinline__ void upk2(u64t v, float& lo, float& hi) {
    asm("mov.b64 {%0,%1},%2;" : "=f"(lo), "=f"(hi) : "l"(v));
}
__device__ __forceinline__ void fma2(u64t& d, u64t a, u64t b) {
    asm("fma.rn.f32x2 %0,%1,%2,%0;" : "+l"(d) : "l"(a), "l"(b));
}
// bf16x2 word -> packed f32x2 (bf16->f32 is a 16-bit shift)
__device__ __forceinline__ u64t upk_bf(unsigned w) {
    return pk2(__uint_as_float(w << 16), __uint_as_float(w & 0xffff0000u));
}
__device__ __forceinline__ unsigned pkbf(float a, float b) {
    __nv_bfloat162 p = __floats2bfloat162_rn(a, b);
    return *(unsigned*)&p;
}

// ============================================================
// Kernel 0: transpose + convert all weights to bf16 (n-major)
// ============================================================
__global__ void k_wtb(const float* __restrict__ w1, const float* __restrict__ w2,
                      const float* __restrict__ wq, const float* __restrict__ wk,
                      const float* __restrict__ wv)
{
    __shared__ float t[32][33];
    const int which = blockIdx.z;
    const float* srcs[5] = { w1, w2, wq, wk, wv };
    __nv_bfloat16* dsts[5] = { g_w1tb, g_w2tb, g_wqtb, g_wktb, g_wvtb };
    const int Rs[5] = { 128, 512, 128, 128, 128 };
    const int Cs[5] = { 512, 128, 128, 128, 128 };
    const float* src = srcs[which];
    __nv_bfloat16* dst = dsts[which];
    const int R = Rs[which], C = Cs[which];
    const int r0 = blockIdx.y * 32, c0 = blockIdx.x * 32;
    if (r0 >= R || c0 >= C) return;
    const int lx = threadIdx.x, ly = threadIdx.y;
#pragma unroll
    for (int i = 0; i < 32; i += 8)
        t[ly + i][lx] = src[(size_t)(r0 + ly + i) * C + c0 + lx];
    __syncthreads();
#pragma unroll
    for (int i = 0; i < 32; i += 8)
        dst[(size_t)(c0 + ly + i) * R + r0 + lx] = __float2bfloat16(t[lx][ly + i]);
}

// ============================================================
// mma pass via ldmatrix (unchanged from R16)
// ============================================================
#define A_W 68

__device__ __forceinline__ void f_mma_pass(unsigned sbase, int aOff, int bOff,
                                           float acc[2][4][4],
                                           int wm, int wn, int lane)
{
    const int lm = lane & 7, lq = lane >> 3;
    const int arow = wm * 32 + (lq & 1) * 8 + lm;
    const int akw  = (lq >> 1) * 4;
    const int brow = wn * 32 + (lq >> 1) * 8 + lm;
    const int bkw  = (lq & 1) * 4;
    unsigned a0 = sbase + (unsigned)((aOff + arow * A_W + akw) << 2);
    unsigned a1 = a0 + 16 * A_W * 4;
    unsigned b0 = sbase + (unsigned)((bOff + brow * A_W + bkw) << 2);
    unsigned b1 = b0 + 16 * A_W * 4;
#pragma unroll
    for (int s = 0; s < 8; s++) {
        unsigned aw0[4], aw1[4], bw0[4], bw1[4];
        ldsm4(aw0, a0 + s * 32);
        ldsm4(aw1, a1 + s * 32);
        ldsm4(bw0, b0 + s * 32);
        ldsm4(bw1, b1 + s * 32);
        mma16(acc[0][0], aw0, bw0);
        mma16(acc[1][0], aw1, bw0);
        mma16(acc[0][1], aw0, bw0 + 2);
        mma16(acc[1][1], aw1, bw0 + 2);
        mma16(acc[0][2], aw0, bw1);
        mma16(acc[1][2], aw1, bw1);
        mma16(acc[0][3], aw0, bw1 + 2);
        mma16(acc[1][3], aw1, bw1 + 2);
    }
}

__device__ __forceinline__ void f_mma_pass2(unsigned sbase, int aOff,
                                            int bOffX, int bOffY,
                                            float accX[2][4][4], float accY[2][4][4],
                                            int wm, int wn, int lane)
{
    const int lm = lane & 7, lq = lane >> 3;
    const int arow = wm * 32 + (lq & 1) * 8 + lm;
    const int akw  = (lq >> 1) * 4;
    const int brow = wn * 32 + (lq >> 1) * 8 + lm;
    const int bkw  = (lq & 1) * 4;
    unsigned a0 = sbase + (unsigned)((aOff + arow * A_W + akw) << 2);
    unsigned a1 = a0 + 16 * A_W * 4;
    unsigned bx0 = sbase + (unsigned)((bOffX + brow * A_W + bkw) << 2);
    unsigned bx1 = bx0 + 16 * A_W * 4;
    unsigned by0 = sbase + (unsigned)((bOffY + brow * A_W + bkw) << 2);
    unsigned by1 = by0 + 16 * A_W * 4;
#pragma unroll
    for (int s = 0; s < 8; s++) {
        unsigned aw0[4], aw1[4], bwx0[4], bwx1[4], bwy0[4], bwy1[4];
        ldsm4(aw0, a0 + s * 32);
        ldsm4(aw1, a1 + s * 32);
        ldsm4(bwx0, bx0 + s * 32);
        ldsm4(bwx1, bx1 + s * 32);
        ldsm4(bwy0, by0 + s * 32);
        ldsm4(bwy1, by1 + s * 32);
        mma16(accX[0][0], aw0, bwx0);     mma16(accX[1][0], aw1, bwx0);
        mma16(accX[0][1], aw0, bwx0 + 2); mma16(accX[1][1], aw1, bwx0 + 2);
        mma16(accX[0][2], aw0, bwx1);     mma16(accX[1][2], aw1, bwx1);
        mma16(accX[0][3], aw0, bwx1 + 2); mma16(accX[1][3], aw1, bwx1 + 2);
        mma16(accY[0][0], aw0, bwy0);     mma16(accY[1][0], aw1, bwy0);
        mma16(accY[0][1], aw0, bwy0 + 2); mma16(accY[1][1], aw1, bwy0 + 2);
        mma16(accY[0][2], aw0, bwy1);     mma16(accY[1][2], aw1, bwy1);
        mma16(accY[0][3], aw0, bwy1 + 2); mma16(accY[1][3], aw1, bwy1 + 2);
    }
}

// ============================================================
// MEGA KERNEL: QKV + rotary + attention + LN1 + FFN + LN2
// bf16 K/V/Q attention buffers (word pitch KB_W).
// smem words (peak 26112 = 104448 B, 2 CTAs/SM):
//  QKV:   A 4352 @0 | Bk 8704 @4352 | Bv 8704 @13056  (wq -> @4352 after pass1)
//  Attn:  Kb bf16 @0 | Vb @4352 | Qb @8704  (4352 words each)
//  FFN:   x1b @0 | Hc @4352 | B0(w1) @8704 | B1(w2) @17408
//  Epi:   T f32 8448 @0
// ============================================================
#define FB0 4352
#define FB1 13056
#define KB_W 68
#define AT_K 0
#define AT_V 4352
#define AT_Q 8704
#define MG_X1B 0
#define MG_HC  4352
#define MG_B0  8704
#define MG_B1  17408
#define MG_WORDS 26112
#define MG_BYTES (MG_WORDS*4)
#define FP 132

__device__ __forceinline__ void f_stage_w(unsigned* sm_u, int dstoff,
                                          const __nv_bfloat16* W, int tid)
{
#pragma unroll
    for (int j = 0; j < 8; j++) {
        const int i = tid + j * 256;
        const int row = i >> 4, u = i & 15;
        cp16(&sm_u[dstoff + row * A_W + u * 4], &W[(size_t)row * CDIM + u * 8]);
    }
    cp_commit();
}

__device__ __forceinline__ void ff_stage_w1(unsigned* sm_u, int nt, int tid)
{
#pragma unroll
    for (int j = 0; j < 8; j++) {
        const int i = tid + j * 256;
        const int row = i >> 4, u = i & 15;
        cp16(&sm_u[MG_B0 + row * A_W + u * 4],
             &g_w1tb[(size_t)(nt * 128 + row) * CDIM + u * 8]);
    }
    cp_commit();
}
__device__ __forceinline__ void ff_stage_w2(unsigned* sm_u, int nt, int tid)
{
#pragma unroll
    for (int j = 0; j < 8; j++) {
        const int i = tid + j * 256;
        const int row = i >> 4, u = i & 15;
        cp16(&sm_u[MG_B1 + row * A_W + u * 4],
             &g_w2tb[(size_t)row * FFND + nt * 128 + u * 8]);
    }
    cp_commit();
}

__device__ __forceinline__ void unpk16(uint4 a, uint4 b, float* f)
{
    unsigned w[8] = { a.x, a.y, a.z, a.w, b.x, b.y, b.z, b.w };
#pragma unroll
    for (int i = 0; i < 8; i++) {
        f[2 * i]     = __uint_as_float(w[i] << 16);
        f[2 * i + 1] = __uint_as_float(w[i] & 0xffff0000u);
    }
}

__global__ __launch_bounds__(256, 2)
void k_block(const float* __restrict__ x,
             const float* __restrict__ bq, const float* __restrict__ bk,
             const float* __restrict__ bv,
             const float* __restrict__ ln1g, const float* __restrict__ ln1b,
             const float* __restrict__ b1, const float* __restrict__ b2,
             const float* __restrict__ ln2g, const float* __restrict__ ln2b,
             float* __restrict__ out)
{
    extern __shared__ unsigned sm_u[];
    float* smf = (float*)sm_u;
    __shared__ float sinT[SEQ][8];
    __shared__ float cosT[SEQ][8];

    const unsigned sbase = (unsigned)__cvta_generic_to_shared(sm_u);
    const int tid = threadIdx.x;
    const int warp = tid >> 5, lane = tid & 31;
    const int wm = warp >> 2, wn = warp & 3;
    const int g = lane >> 2, t = lane & 3;
    const int m0 = blockIdx.x * 64;

    if (tid < SEQ * 8) {
        const int s = tid >> 3, j = tid & 7;
        const float ang = powf(10000.0f, -(float)j / 7.0f);
        float sv, cv;
        sincosf((float)s * ang, &sv, &cv);
        sinT[s][j] = sv;
        cosT[s][j] = cv;
    }

    // ================= Phase 1: QKV GEMM =================
    f_stage_w(sm_u, FB0, g_wktb, tid);
    f_stage_w(sm_u, FB1, g_wvtb, tid);
    {
        const int row = tid >> 2;
        const int seg = tid & 3;
        const int r = m0 + row;
        const float* src = &x[(size_t)(r & 31) * (NLOC * CDIM)
                              + (size_t)(r >> 5) * CDIM + seg * 32];
        unsigned* dstw = &sm_u[row * A_W + seg * 16];
#pragma unroll
        for (int q = 0; q < 8; q++) {
            float4 v = *(const float4*)(src + q * 4);
            dstw[q * 2]     = pkbf(v.x, v.y);
            dstw[q * 2 + 1] = pkbf(v.z, v.w);
        }
    }
    cp_wait<0>();
    __syncthreads();

    float acc[3][2][4][4];
#pragma unroll
    for (int w = 0; w < 3; w++)
#pragma unroll
        for (int i = 0; i < 2; i++)
#pragma unroll
            for (int j = 0; j < 4; j++)
#pragma unroll
                for (int q = 0; q < 4; q++) acc[w][i][j][q] = 0.0f;

    f_mma_pass2(sbase, 0, FB0, FB1, acc[0], acc[1], wm, wn, lane);
    __syncthreads();

    f_stage_w(sm_u, FB0, g_wqtb, tid);
    cp_wait<0>();
    __syncthreads();
    f_mma_pass(sbase, 0, FB0, acc[2], wm, wn, lane);
    __syncthreads();

    // epilogue: acc + bias -> K/V/Q bf16 tiles
    {
        const float* biases[3] = { bk, bv, bq };
        const int dsts[3] = { AT_K, AT_V, AT_Q };
#pragma unroll
        for (int w = 0; w < 3; w++) {
            const int dst = dsts[w];
            const float* BIAS = biases[w];
#pragma unroll
            for (int nf = 0; nf < 4; nf++) {
                const int col = wn * 32 + nf * 8 + 2 * t;
                const float2 bv2 = *(const float2*)&BIAS[col];
#pragma unroll
                for (int mf = 0; mf < 2; mf++) {
                    const int row0 = wm * 32 + mf * 16 + g;
                    sm_u[dst + row0 * KB_W + (col >> 1)] =
                        pkbf(acc[w][mf][nf][0] + bv2.x, acc[w][mf][nf][1] + bv2.y);
                    sm_u[dst + (row0 + 8) * KB_W + (col >> 1)] =
                        pkbf(acc[w][mf][nf][2] + bv2.x, acc[w][mf][nf][3] + bv2.y);
                }
            }
        }
    }
    __syncthreads();

    // ================= Phase 2: rotary (bf16 in/out) + attention =================
#pragma unroll
    for (int task = tid; task < 64 * NHEAD; task += 256) {
        const int row = task >> 3, h = task & 7;
        const int s = row & 31;
        uint4 qa = *(const uint4*)&sm_u[AT_Q + row * KB_W + h * 8];
        uint4 qb = *(const uint4*)&sm_u[AT_Q + row * KB_W + h * 8 + 4];
        uint4 ka = *(const uint4*)&sm_u[AT_K + row * KB_W + h * 8];
        uint4 kb = *(const uint4*)&sm_u[AT_K + row * KB_W + h * 8 + 4];
        float tq[HD], tk[HD];
        unpk16(qa, qb, tq);
        unpk16(ka, kb, tk);
        float rq[HD], rk[HD];
#pragma unroll
        for (int d = 0; d < HD; d++) {
            const float sv = sinT[s][d >> 1];
            const float cv = cosT[s][d >> 1];
            const int pc = (d < 8) ? (2 * d + 1) : (2 * d - 16);
            const float sgn = (d < 8) ? -1.0f : 1.0f;
            rq[d] = tq[d] * cv + sgn * tq[pc] * sv;
            rk[d] = tk[d] * cv + sgn * tk[pc] * sv;
        }
        uint4 oq0, oq1, ok0, ok1;
        oq0.x = pkbf(rq[0], rq[1]);   oq0.y = pkbf(rq[2], rq[3]);
        oq0.z = pkbf(rq[4], rq[5]);   oq0.w = pkbf(rq[6], rq[7]);
        oq1.x = pkbf(rq[8], rq[9]);   oq1.y = pkbf(rq[10], rq[11]);
        oq1.z = pkbf(rq[12], rq[13]); oq1.w = pkbf(rq[14], rq[15]);
        ok0.x = pkbf(rk[0], rk[1]);   ok0.y = pkbf(rk[2], rk[3]);
        ok0.z = pkbf(rk[4], rk[5]);   ok0.w = pkbf(rk[6], rk[7]);
        ok1.x = pkbf(rk[8], rk[9]);   ok1.y = pkbf(rk[10], rk[11]);
        ok1.z = pkbf(rk[12], rk[13]); ok1.w = pkbf(rk[14], rk[15]);
        *(uint4*)&sm_u[AT_Q + row * KB_W + h * 8]     = oq0;
        *(uint4*)&sm_u[AT_Q + row * KB_W + h * 8 + 4] = oq1;
        *(uint4*)&sm_u[AT_K + row * KB_W + h * 8]     = ok0;
        *(uint4*)&sm_u[AT_K + row * KB_W + h * 8 + 4] = ok1;
    }
    __syncthreads();

    const int h = warp;
    const float decay = log1pf(-exp2f(-(1.0f + 3.0f * (float)h / 8.0f)));

#pragma unroll
    for (int l = 0; l < 2; l++) {
        const int qrow = l * 32 + lane;

        u64t q2[8];
        {
            uint4 qa = *(const uint4*)&sm_u[AT_Q + qrow * KB_W + h * 8];
            uint4 qb = *(const uint4*)&sm_u[AT_Q + qrow * KB_W + h * 8 + 4];
            q2[0] = upk_bf(qa.x); q2[1] = upk_bf(qa.y);
            q2[2] = upk_bf(qa.z); q2[3] = upk_bf(qa.w);
            q2[4] = upk_bf(qb.x); q2[5] = upk_bf(qb.y);
            q2[6] = upk_bf(qb.z); q2[7] = upk_bf(qb.w);
        }

        float p[SEQ];
        float mx = -1e30f;
#pragma unroll
        for (int j = 0; j < SEQ; j++) {
            uint4 ka = *(const uint4*)&sm_u[AT_K + (l * 32 + j) * KB_W + h * 8];
            uint4 kb = *(const uint4*)&sm_u[AT_K + (l * 32 + j) * KB_W + h * 8 + 4];
            u64t s2a = 0ull, s2b = 0ull;
            fma2(s2a, q2[0], upk_bf(ka.x)); fma2(s2b, q2[1], upk_bf(ka.y));
            fma2(s2a, q2[2], upk_bf(ka.z)); fma2(s2b, q2[3], upk_bf(ka.w));
            fma2(s2a, q2[4], upk_bf(kb.x)); fma2(s2b, q2[5], upk_bf(kb.y));
            fma2(s2a, q2[6], upk_bf(kb.z)); fma2(s2b, q2[7], upk_bf(kb.w));
            float la, ha, lb, hb;
            upk2(s2a, la, ha);
            upk2(s2b, lb, hb);
            const float dot = (la + lb) + (ha + hb) + fabsf((float)(lane - j)) * decay;
            p[j] = dot;
            mx = fmaxf(mx, dot);
        }
        float sum = 0.0f;
#pragma unroll
        for (int j = 0; j < SEQ; j++) { p[j] = expf(p[j] - mx); sum += p[j]; }
        const float inv = 1.0f / sum;

        u64t o2[8];
#pragma unroll
        for (int i = 0; i < 8; i++) o2[i] = 0ull;
#pragma unroll
        for (int j = 0; j < SEQ; j++) {
            uint4 va = *(const uint4*)&sm_u[AT_V + (l * 32 + j) * KB_W + h * 8];
            uint4 vb = *(const uint4*)&sm_u[AT_V + (l * 32 + j) * KB_W + h * 8 + 4];
            const u64t pj2 = pk2(p[j], p[j]);
            fma2(o2[0], upk_bf(va.x), pj2); fma2(o2[1], upk_bf(va.y), pj2);
            fma2(o2[2], upk_bf(va.z), pj2); fma2(o2[3], upk_bf(va.w), pj2);
            fma2(o2[4], upk_bf(vb.x), pj2); fma2(o2[5], upk_bf(vb.y), pj2);
            fma2(o2[6], upk_bf(vb.z), pj2); fma2(o2[7], upk_bf(vb.w), pj2);
        }
        uint4 ow0, ow1;
        {
            float lo, hi;
            upk2(o2[0], lo, hi); ow0.x = pkbf(lo * inv, hi * inv);
            upk2(o2[1], lo, hi); ow0.y = pkbf(lo * inv, hi * inv);
            upk2(o2[2], lo, hi); ow0.z = pkbf(lo * inv, hi * inv);
            upk2(o2[3], lo, hi); ow0.w = pkbf(lo * inv, hi * inv);
            upk2(o2[4], lo, hi); ow1.x = pkbf(lo * inv, hi * inv);
            upk2(o2[5], lo, hi); ow1.y = pkbf(lo * inv, hi * inv);
            upk2(o2[6], lo, hi); ow1.z = pkbf(lo * inv, hi * inv);
            upk2(o2[7], lo, hi); ow1.w = pkbf(lo * inv, hi * inv);
        }
        *(uint4*)&sm_u[AT_Q + qrow * KB_W + h * 8]     = ow0;
        *(uint4*)&sm_u[AT_Q + qrow * KB_W + h * 8 + 4] = ow1;
    }
    __syncthreads();

    // ====== Phase 3: residual + LN1 -> registers (xres) + smem x1b (bf16) ======
    float xres[8][4];
#pragma unroll
    for (int rr = 0; rr < 8; rr++) {
        const int row = warp * 8 + rr;
        const int r = m0 + row;
        const int c = lane * 4;
        const unsigned ow0 = sm_u[AT_Q + row * KB_W + lane * 2];
        const unsigned ow1 = sm_u[AT_Q + row * KB_W + lane * 2 + 1];
        float4 xv = *(const float4*)&x[(size_t)(r & 31) * (NLOC * CDIM) + (size_t)(r >> 5) * CDIM + c];
        float v0 = __uint_as_float(ow0 << 16)          + xv.x;
        float v1 = __uint_as_float(ow0 & 0xffff0000u)  + xv.y;
        float v2 = __uint_as_float(ow1 << 16)          + xv.z;
        float v3 = __uint_as_float(ow1 & 0xffff0000u)  + xv.w;
        float sum = v0 + v1 + v2 + v3;
        float sq  = v0 * v0 + v1 * v1 + v2 * v2 + v3 * v3;
#pragma unroll
        for (int off = 16; off > 0; off >>= 1) {
            sum += __shfl_xor_sync(0xffffffffu, sum, off);
            sq  += __shfl_xor_sync(0xffffffffu, sq,  off);
        }
        const float mu  = sum * (1.0f / 128.0f);
        const float var = sq * (1.0f / 128.0f) - mu * mu;
        const float wnr = rsqrtf(var + 1e-5f);
        float4 g4 = *(const float4*)&ln1g[c];
        float4 b4 = *(const float4*)&ln1b[c];
        float o0 = (v0 - mu) * wnr * g4.x + b4.x;
        float o1 = (v1 - mu) * wnr * g4.y + b4.y;
        float o2v = (v2 - mu) * wnr * g4.z + b4.z;
        float o3 = (v3 - mu) * wnr * g4.w + b4.w;
        xres[rr][0] = o0; xres[rr][1] = o1; xres[rr][2] = o2v; xres[rr][3] = o3;
        sm_u[MG_X1B + row * A_W + lane * 2]     = pkbf(o0, o1);
        sm_u[MG_X1B + row * A_W + lane * 2 + 1] = pkbf(o2v, o3);
    }
    __syncthreads();

    // ======= Phase 4: FFN, fixed-role double buffer (B0=w1, B1=w2) =======
    float acc2[2][4][4];
#pragma unroll
    for (int i = 0; i < 2; i++)
#pragma unroll
        for (int j = 0; j < 4; j++)
#pragma unroll
            for (int q = 0; q < 4; q++) acc2[i][j][q] = 0.0f;

    ff_stage_w1(sm_u, 0, tid);
    cp_wait<0>();
    __syncthreads();

#pragma unroll 1
    for (int nt = 0; nt < 4; nt++) {
        ff_stage_w2(sm_u, nt, tid);

        float accH[2][4][4];
#pragma unroll
        for (int i = 0; i < 2; i++)
#pragma unroll
            for (int j = 0; j < 4; j++)
#pragma unroll
                for (int q = 0; q < 4; q++) accH[i][j][q] = 0.0f;
        f_mma_pass(sbase, MG_X1B, MG_B0, accH, wm, wn, lane);

#pragma unroll
        for (int nf = 0; nf < 4; nf++) {
            const int col = wn * 32 + nf * 8 + 2 * t;
            const float2 bb = *(const float2*)&b1[nt * 128 + col];
#pragma unroll
            for (int mf = 0; mf < 2; mf++) {
                const int row0 = wm * 32 + mf * 16 + g;
                float h00 = fmaxf(accH[mf][nf][0] + bb.x, 0.0f);
                float h01 = fmaxf(accH[mf][nf][1] + bb.y, 0.0f);
                float h10 = fmaxf(accH[mf][nf][2] + bb.x, 0.0f);
                float h11 = fmaxf(accH[mf][nf][3] + bb.y, 0.0f);
                sm_u[MG_HC + row0 * A_W + (col >> 1)]       = pkbf(h00, h01);
                sm_u[MG_HC + (row0 + 8) * A_W + (col >> 1)] = pkbf(h10, h11);
            }
        }
        cp_wait<0>();
        __syncthreads();

        if (nt < 3)
            ff_stage_w1(sm_u, nt + 1, tid);

        f_mma_pass(sbase, MG_HC, MG_B1, acc2, wm, wn, lane);

        cp_wait<0>();
        __syncthreads();
    }

    // ================= Phase 5: epilogue =================
    float* T = smf;
#pragma unroll
    for (int nf = 0; nf < 4; nf++) {
        const int col = wn * 32 + nf * 8 + 2 * t;
        const float2 bb = *(const float2*)&b2[col];
#pragma unroll
        for (int mf = 0; mf < 2; mf++) {
            const int row0 = wm * 32 + mf * 16 + g;
            float2 o0, o1;
            o0.x = acc2[mf][nf][0] + bb.x; o0.y = acc2[mf][nf][1] + bb.y;
            o1.x = acc2[mf][nf][2] + bb.x; o1.y = acc2[mf][nf][3] + bb.y;
            *(float2*)&T[row0 * FP + col] = o0;
            *(float2*)&T[(row0 + 8) * FP + col] = o1;
        }
    }
    __syncthreads();

#pragma unroll
    for (int rr = 0; rr < 8; rr++) {
        const int row = warp * 8 + rr;
        const int r = m0 + row;
        const int c = lane * 4;
        float4 v = *(const float4*)&T[row * FP + c];
        float v0 = v.x + xres[rr][0], v1 = v.y + xres[rr][1];
        float v2 = v.z + xres[rr][2], v3 = v.w + xres[rr][3];
        float sum = v0 + v1 + v2 + v3;
        float sq  = v0 * v0 + v1 * v1 + v2 * v2 + v3 * v3;
#pragma unroll
        for (int off = 16; off > 0; off >>= 1) {
            sum += __shfl_xor_sync(0xffffffffu, sum, off);
            sq  += __shfl_xor_sync(0xffffffffu, sq,  off);
        }
        const float mu  = sum * (1.0f / 128.0f);
        const float var = sq * (1.0f / 128.0f) - mu * mu;
        const float wnr = rsqrtf(var + 1e-5f);
        float4 g4 = *(const float4*)&ln2g[c];
        float4 b4 = *(const float4*)&ln2b[c];
        float4 o;
        o.x = (v0 - mu) * wnr * g4.x + b4.x;
        o.y = (v1 - mu) * wnr * g4.y + b4.y;
        o.z = (v2 - mu) * wnr * g4.z + b4.z;
        o.w = (v3 - mu) * wnr * g4.w + b4.w;
        const int nn = r >> 5;
        const int ss = r & 31;
        *(float4*)&out[(size_t)ss * NLOC * CDIM + (size_t)nn * CDIM + c] = o;
    }
}

// ============================================================
extern "C" void kernel_launch(void* const* d_in, const int* in_sizes, int n_in,
                              void* d_out, int out_size)
{
    (void)in_sizes; (void)n_in; (void)out_size;
    const float* x    = (const float*)d_in[0];
    const float* wq   = (const float*)d_in[1];
    const float* bq   = (const float*)d_in[2];
    const float* wk   = (const float*)d_in[3];
    const float* bk   = (const float*)d_in[4];
    const float* wv   = (const float*)d_in[5];
    const float* bv   = (const float*)d_in[6];
    const float* ln1g = (const float*)d_in[7];
    const float* ln1b = (const float*)d_in[8];
    const float* w1   = (const float*)d_in[9];
    const float* b1   = (const float*)d_in[10];
    const float* w2   = (const float*)d_in[11];
    const float* b2   = (const float*)d_in[12];
    const float* ln2g = (const float*)d_in[13];
    const float* ln2b = (const float*)d_in[14];
    float* out = (float*)d_out;

    cudaFuncSetAttribute(k_block, cudaFuncAttributeMaxDynamicSharedMemorySize, MG_BYTES);

    dim3 tg(16, 16, 5), tb(32, 8);
    k_wtb<<<tg, tb>>>(w1, w2, wq, wk, wv);

    k_block<<<MROWS / 64, 256, MG_BYTES>>>(x, bq, bk, bv, ln1g, ln1b,
                                           b1, b2, ln2g, ln2b, out);
}